// round 1
// baseline (speedup 1.0000x reference)
#include <cuda_runtime.h>
#include <math.h>

#define BATCH 2
#define SEQ   2048
#define DIM   1024
#define NHEAD 16
#define HDIM  64
#define NTOK  (BATCH*SEQ)   // 4096

// ---------------------------------------------------------------------------
// Scratch (static device allocations — allowed; runtime alloc is not)
// ---------------------------------------------------------------------------
__device__ float g_zn  [NTOK*DIM];
__device__ float g_cn  [NTOK*DIM];
__device__ float g_hf  [NTOK*2*DIM];
__device__ float g_dzl [NTOK*DIM];
__device__ float g_catg[NTOK*2*DIM];
__device__ float g_gh  [NTOK*DIM];
__device__ float g_corr[NTOK*DIM];
__device__ float g_dz  [NTOK*DIM];
__device__ float g_zc  [NTOK*2*DIM];
__device__ float g_Q   [NTOK*DIM];
__device__ float g_K   [NTOK*DIM];
__device__ float g_V   [NTOK*DIM];
__device__ float g_attn[NTOK*DIM];
__device__ float g_ctx [NTOK*DIM];
__device__ float g_z1  [NTOK*DIM];
__device__ float g_cat3[NTOK*3*DIM];
__device__ float g_hcu [NTOK*2*DIM];
__device__ float g_z1n [NTOK*DIM];
__device__ float g_h4  [NTOK*4*DIM];

// ---------------------------------------------------------------------------
// RMSNorm: out = x * rsqrt(mean(x^2)+eps) * w      (one row per block, D=1024)
// ---------------------------------------------------------------------------
__global__ void rms_kernel(const float* __restrict__ x, const float* __restrict__ w,
                           float* __restrict__ o)
{
    int row = blockIdx.x;
    int t   = threadIdx.x;                       // 256 threads, 4 floats each
    const float4* xr = (const float4*)(x + (size_t)row * DIM);
    float4 v = xr[t];
    float ss = v.x*v.x + v.y*v.y + v.z*v.z + v.w*v.w;

    __shared__ float red[256];
    red[t] = ss;
    __syncthreads();
    for (int s = 128; s > 0; s >>= 1) {
        if (t < s) red[t] += red[t + s];
        __syncthreads();
    }
    float inv = rsqrtf(red[0] * (1.0f / DIM) + 1e-6f);
    float4 wv = ((const float4*)w)[t];
    float4 ov;
    ov.x = v.x * inv * wv.x;
    ov.y = v.y * inv * wv.y;
    ov.z = v.z * inv * wv.z;
    ov.w = v.w * inv * wv.w;
    ((float4*)(o + (size_t)row * DIM))[t] = ov;
}

// ---------------------------------------------------------------------------
// Concats (row-wise)
// ---------------------------------------------------------------------------
__global__ void concat2_kernel(const float* __restrict__ A, const float* __restrict__ B,
                               float* __restrict__ O, int KA, int KB)
{
    int row = blockIdx.x;
    float* orow = O + (size_t)row * (KA + KB);
    const float* a = A + (size_t)row * KA;
    const float* b = B + (size_t)row * KB;
    for (int c = threadIdx.x; c < KA; c += blockDim.x) orow[c] = a[c];
    for (int c = threadIdx.x; c < KB; c += blockDim.x) orow[KA + c] = b[c];
}

__global__ void concat3_kernel(const float* __restrict__ A, const float* __restrict__ B,
                               const float* __restrict__ C, float* __restrict__ O,
                               int KA, int KB, int KC)
{
    int row = blockIdx.x;
    float* orow = O + (size_t)row * (KA + KB + KC);
    const float* a = A + (size_t)row * KA;
    const float* b = B + (size_t)row * KB;
    const float* c = C + (size_t)row * KC;
    for (int i = threadIdx.x; i < KA; i += blockDim.x) orow[i] = a[i];
    for (int i = threadIdx.x; i < KB; i += blockDim.x) orow[KA + i] = b[i];
    for (int i = threadIdx.x; i < KC; i += blockDim.x) orow[KA + KB + i] = c[i];
}

// ---------------------------------------------------------------------------
// Pointwise
// ---------------------------------------------------------------------------
__global__ void dz_kernel(const float* __restrict__ a, const float* __restrict__ b,
                          const float* __restrict__ dt, float* __restrict__ o, int n)
{
    int i = blockIdx.x * blockDim.x + threadIdx.x;
    if (i < n) o[i] = dt[0] * (a[i] + b[i]);
}

__global__ void add3_kernel(const float* __restrict__ a, const float* __restrict__ b,
                            const float* __restrict__ c, float* __restrict__ o, int n)
{
    int i = blockIdx.x * blockDim.x + threadIdx.x;
    if (i < n) o[i] = a[i] + b[i] + c[i];
}

// ---------------------------------------------------------------------------
// GEMM: C[m][n] = act( sum_k A[m][k]*W[n][k] + bias[n] ) + res[m][n]
// A row-major [M,K], W row-major [N,K] (== x @ w.T). 64x64 tile, BK=16,
// 256 threads, 4x4 micro-tile per thread. M%64==0, N%64==0, K%16==0.
// ACT: 0 none, 1 silu, 2 tanh
// ---------------------------------------------------------------------------
template<int ACT, bool HAS_BIAS, bool HAS_RES>
__global__ void gemm_kernel(const float* __restrict__ A, const float* __restrict__ W,
                            const float* __restrict__ bias, const float* __restrict__ res,
                            float* __restrict__ C, int M, int N, int K)
{
    __shared__ float As[16][64];   // [k][m]
    __shared__ float Ws[16][64];   // [k][n]

    int bm = blockIdx.y * 64;
    int bn = blockIdx.x * 64;
    int tid = threadIdx.x;
    int ty = tid >> 4, tx = tid & 15;

    int lrow = tid >> 2;            // 0..63
    int lcol = (tid & 3) * 4;       // 0,4,8,12

    const float* Aload = A + (size_t)(bm + lrow) * K + lcol;
    const float* Wload = W + (size_t)(bn + lrow) * K + lcol;

    float acc[4][4] = {};

    for (int k0 = 0; k0 < K; k0 += 16) {
        float4 av = *(const float4*)(Aload + k0);
        float4 wv = *(const float4*)(Wload + k0);
        As[lcol + 0][lrow] = av.x; As[lcol + 1][lrow] = av.y;
        As[lcol + 2][lrow] = av.z; As[lcol + 3][lrow] = av.w;
        Ws[lcol + 0][lrow] = wv.x; Ws[lcol + 1][lrow] = wv.y;
        Ws[lcol + 2][lrow] = wv.z; Ws[lcol + 3][lrow] = wv.w;
        __syncthreads();

        #pragma unroll
        for (int kk = 0; kk < 16; kk++) {
            float4 a = *(const float4*)(&As[kk][ty * 4]);
            float4 b = *(const float4*)(&Ws[kk][tx * 4]);
            float ar[4] = {a.x, a.y, a.z, a.w};
            float br[4] = {b.x, b.y, b.z, b.w};
            #pragma unroll
            for (int i = 0; i < 4; i++)
                #pragma unroll
                for (int j = 0; j < 4; j++)
                    acc[i][j] += ar[i] * br[j];
        }
        __syncthreads();
    }

    #pragma unroll
    for (int i = 0; i < 4; i++) {
        int row = bm + ty * 4 + i;
        #pragma unroll
        for (int j = 0; j < 4; j++) {
            int col = bn + tx * 4 + j;
            float v = acc[i][j];
            if (HAS_BIAS) v += bias[col];
            if (ACT == 1) v = v / (1.0f + __expf(-v));     // silu
            else if (ACT == 2) v = tanhf(v);
            if (HAS_RES) v += res[(size_t)row * N + col];
            C[(size_t)row * N + col] = v;
        }
    }
}

// ---------------------------------------------------------------------------
// Sigmoid attention (flash-style single pass, no softmax max needed).
// Q,K,V laid out [NTOK, DIM] with head h at cols [h*64, h*64+64).
// Block: 64 query rows for one (b,h); KV tiles of 32.
// attn = (sigmoid(QK^T * scale) @ V) / max(rowsum, 1)
// ---------------------------------------------------------------------------
__global__ void attn_kernel(const float* __restrict__ Q, const float* __restrict__ K,
                            const float* __restrict__ V, const float* __restrict__ temp,
                            float* __restrict__ O)
{
    __shared__ float Qs[64][65];
    __shared__ float Ks[32][65];
    __shared__ float Vs[32][68];
    __shared__ float Ssm[64][33];
    __shared__ float rowsum[64];

    int b = blockIdx.z, h = blockIdx.y;
    int q0 = blockIdx.x * 64;
    int tid = threadIdx.x;
    int ty = tid >> 4, tx = tid & 15;

    const float scale = 0.125f * temp[0];   // HD^-0.5 = 1/8
    const size_t baseq  = ((size_t)(b * SEQ + q0)) * DIM + h * HDIM;
    const size_t basekv = ((size_t)(b * SEQ)) * DIM + h * HDIM;

    // Load Q tile: 64 rows x 64 cols
    #pragma unroll
    for (int it = 0; it < 4; it++) {
        int fid = tid + it * 256;          // 0..1023 float4s
        int r = fid >> 4, c4 = (fid & 15) * 4;
        float4 v = *(const float4*)(Q + baseq + (size_t)r * DIM + c4);
        Qs[r][c4] = v.x; Qs[r][c4 + 1] = v.y; Qs[r][c4 + 2] = v.z; Qs[r][c4 + 3] = v.w;
    }
    if (tid < 64) rowsum[tid] = 0.0f;

    float oacc[4][4] = {};

    for (int m0 = 0; m0 < SEQ; m0 += 32) {
        __syncthreads();   // protect Ks/Vs/Ssm reuse (also orders Qs/rowsum init)
        #pragma unroll
        for (int it = 0; it < 2; it++) {
            int fid = tid + it * 256;      // 0..511 float4s
            int r = fid >> 4, c4 = (fid & 15) * 4;
            float4 kv = *(const float4*)(K + basekv + (size_t)(m0 + r) * DIM + c4);
            Ks[r][c4] = kv.x; Ks[r][c4 + 1] = kv.y; Ks[r][c4 + 2] = kv.z; Ks[r][c4 + 3] = kv.w;
            float4 vv = *(const float4*)(V + basekv + (size_t)(m0 + r) * DIM + c4);
            Vs[r][c4] = vv.x; Vs[r][c4 + 1] = vv.y; Vs[r][c4 + 2] = vv.z; Vs[r][c4 + 3] = vv.w;
        }
        __syncthreads();

        // S tile: rows ty*4..+3, cols tx*2..+1
        float s0[4] = {}, s1[4] = {};
        int m = tx * 2;
        #pragma unroll 16
        for (int d = 0; d < 64; d++) {
            float b0 = Ks[m][d], b1 = Ks[m + 1][d];
            #pragma unroll
            for (int i = 0; i < 4; i++) {
                float a = Qs[ty * 4 + i][d];
                s0[i] += a * b0;
                s1[i] += a * b1;
            }
        }
        #pragma unroll
        for (int i = 0; i < 4; i++) {
            Ssm[ty * 4 + i][m]     = 1.0f / (1.0f + __expf(-s0[i] * scale));
            Ssm[ty * 4 + i][m + 1] = 1.0f / (1.0f + __expf(-s1[i] * scale));
        }
        __syncthreads();

        if (tid < 64) {
            float rs = 0.0f;
            #pragma unroll
            for (int mm = 0; mm < 32; mm++) rs += Ssm[tid][mm];
            rowsum[tid] += rs;
        }

        // O += Ssm @ Vs   (rows ty*4..+3, hd cols tx*4..+3)
        #pragma unroll
        for (int mm = 0; mm < 32; mm++) {
            float4 v = *(const float4*)(&Vs[mm][tx * 4]);
            #pragma unroll
            for (int i = 0; i < 4; i++) {
                float s = Ssm[ty * 4 + i][mm];
                oacc[i][0] += s * v.x; oacc[i][1] += s * v.y;
                oacc[i][2] += s * v.z; oacc[i][3] += s * v.w;
            }
        }
    }
    __syncthreads();

    #pragma unroll
    for (int i = 0; i < 4; i++) {
        int r = ty * 4 + i;
        float inv = 1.0f / fmaxf(rowsum[r], 1.0f);
        float4 o4 = make_float4(oacc[i][0] * inv, oacc[i][1] * inv,
                                oacc[i][2] * inv, oacc[i][3] * inv);
        *(float4*)(O + baseq + (size_t)r * DIM + tx * 4) = o4;
    }
}

// ---------------------------------------------------------------------------
// Host-side GEMM dispatch
// ---------------------------------------------------------------------------
static void gemm(const float* A, const float* W, const float* bias, const float* res,
                 float* C, int M, int N, int K, int act)
{
    dim3 g(N / 64, M / 64), b(256);
    if (bias && res) {
        // only act==0 needed with residual
        gemm_kernel<0, true, true><<<g, b>>>(A, W, bias, res, C, M, N, K);
    } else if (bias) {
        if (act == 0)      gemm_kernel<0, true, false><<<g, b>>>(A, W, bias, nullptr, C, M, N, K);
        else if (act == 1) gemm_kernel<1, true, false><<<g, b>>>(A, W, bias, nullptr, C, M, N, K);
        else               gemm_kernel<2, true, false><<<g, b>>>(A, W, bias, nullptr, C, M, N, K);
    } else {
        gemm_kernel<0, false, false><<<g, b>>>(A, W, nullptr, nullptr, C, M, N, K);
    }
}

static float* sym(const void* s)
{
    void* p = nullptr;
    cudaGetSymbolAddress(&p, s);
    return (float*)p;
}

extern "C" void kernel_launch(void* const* d_in, const int* in_sizes, int n_in,
                              void* d_out, int out_size)
{
    const float* z     = (const float*)d_in[0];
    const float* conn  = (const float*)d_in[1];
    const float* w_z   = (const float*)d_in[2];
    const float* w_c   = (const float*)d_in[3];
    const float* w_mlp = (const float*)d_in[4];
    const float* f_w1  = (const float*)d_in[5];
    const float* f_b1  = (const float*)d_in[6];
    const float* f_w2  = (const float*)d_in[7];
    const float* f_b2  = (const float*)d_in[8];
    const float* g_w1  = (const float*)d_in[9];
    const float* g_b1  = (const float*)d_in[10];
    const float* g_w2  = (const float*)d_in[11];
    const float* g_b2  = (const float*)d_in[12];
    const float* dt    = (const float*)d_in[13];
    const float* q_w   = (const float*)d_in[14];
    const float* k_w   = (const float*)d_in[15];
    const float* v_w   = (const float*)d_in[16];
    const float* o_w   = (const float*)d_in[17];
    const float* temp  = (const float*)d_in[18];
    const float* cu_w1 = (const float*)d_in[19];
    const float* cu_b1 = (const float*)d_in[20];
    const float* cu_w2 = (const float*)d_in[21];
    const float* cu_b2 = (const float*)d_in[22];
    const float* m_w1  = (const float*)d_in[23];
    const float* m_b1  = (const float*)d_in[24];
    const float* m_w2  = (const float*)d_in[25];
    const float* m_b2  = (const float*)d_in[26];

    float* out_z2 = (float*)d_out;
    float* out_cn = out_z2 + (size_t)NTOK * DIM;
    float* out_zb = out_cn + (size_t)NTOK * DIM;

    float* zn   = sym(g_zn);
    float* cn   = sym(g_cn);
    float* hf   = sym(g_hf);
    float* dzl  = sym(g_dzl);
    float* catg = sym(g_catg);
    float* gh   = sym(g_gh);
    float* corr = sym(g_corr);
    float* dz   = sym(g_dz);
    float* zc   = sym(g_zc);
    float* Qb   = sym(g_Q);
    float* Kb   = sym(g_K);
    float* Vb   = sym(g_V);
    float* attn = sym(g_attn);
    float* ctx  = sym(g_ctx);
    float* z1   = sym(g_z1);
    float* cat3 = sym(g_cat3);
    float* hcu  = sym(g_hcu);
    float* z1n  = sym(g_z1n);
    float* h4   = sym(g_h4);

    const int ND = NTOK * DIM;
    const int PW_BLK = 256;
    const int PW_GRID = ND / PW_BLK;

    // 1. norms
    rms_kernel<<<NTOK, 256>>>(z, w_z, zn);
    rms_kernel<<<NTOK, 256>>>(conn, w_c, cn);

    // 2. vector field F(zn): silu MLP D -> 2D -> D
    gemm(zn, f_w1, f_b1, nullptr, hf, NTOK, 2 * DIM, DIM, 1);        // silu
    gemm(hf, f_w2, f_b2, nullptr, dzl, NTOK, DIM, 2 * DIM, 0);

    // 3. gamma correction: tanh(lin(cat(cn, dz_local))) -> lin
    concat2_kernel<<<NTOK, 256>>>(cn, dzl, catg, DIM, DIM);
    gemm(catg, g_w1, g_b1, nullptr, gh, NTOK, DIM, 2 * DIM, 2);      // tanh
    gemm(gh, g_w2, g_b2, nullptr, corr, NTOK, DIM, DIM, 0);
    dz_kernel<<<PW_GRID, PW_BLK>>>(dzl, corr, dt, dz, ND);

    // 4. attention projections
    concat2_kernel<<<NTOK, 256>>>(zn, cn, zc, DIM, DIM);
    gemm(zc, q_w, nullptr, nullptr, Qb, NTOK, DIM, 2 * DIM, 0);
    gemm(zc, k_w, nullptr, nullptr, Kb, NTOK, DIM, 2 * DIM, 0);
    gemm(zn, v_w, nullptr, nullptr, Vb, NTOK, DIM, DIM, 0);

    // 5. sigmoid attention
    {
        dim3 g(SEQ / 64, NHEAD, BATCH), b(256);
        attn_kernel<<<g, b>>>(Qb, Kb, Vb, temp, attn);
    }
    gemm(attn, o_w, nullptr, nullptr, ctx, NTOK, DIM, DIM, 0);

    // 6. z1 = z + dz + ctx
    add3_kernel<<<PW_GRID, PW_BLK>>>(z, dz, ctx, z1, ND);

    // 7. connection update: conn_new = conn + cu2(silu(cu1(cat(conn,z1,dz))))
    concat3_kernel<<<NTOK, 256>>>(conn, z1, dz, cat3, DIM, DIM, DIM);
    gemm(cat3, cu_w1, cu_b1, nullptr, hcu, NTOK, 2 * DIM, 3 * DIM, 1);   // silu
    gemm(hcu, cu_w2, cu_b2, conn, out_cn, NTOK, DIM, 2 * DIM, 0);        // + residual

    // 8. MLP block: z2 = z1 + m2(silu(m1(rms(z1))))
    rms_kernel<<<NTOK, 256>>>(z1, w_mlp, z1n);
    gemm(z1n, m_w1, m_b1, nullptr, h4, NTOK, 4 * DIM, DIM, 1);           // silu
    gemm(h4, m_w2, m_b2, z1, out_z2, NTOK, DIM, 4 * DIM, 0);             // + residual

    // 9. z_before passthrough
    cudaMemcpyAsync(out_zb, z, (size_t)ND * sizeof(float), cudaMemcpyDeviceToDevice);
}

// round 2
// speedup vs baseline: 2.8478x; 2.8478x over previous
#include <cuda_runtime.h>
#include <math.h>
#include <stdint.h>

#define BATCH 2
#define SEQ   2048
#define DIM   1024
#define NHEAD 16
#define HDIM  64
#define NTOK  (BATCH*SEQ)   // 4096

// ---------------------------------------------------------------------------
// Scratch (static device arrays — runtime alloc is forbidden)
// ---------------------------------------------------------------------------
__device__ float g_zn  [NTOK*DIM];
__device__ float g_cn  [NTOK*DIM];
__device__ float g_hf  [NTOK*2*DIM];
__device__ float g_dzl [NTOK*DIM];
__device__ float g_catg[NTOK*2*DIM];
__device__ float g_gh  [NTOK*DIM];
__device__ float g_corr[NTOK*DIM];
__device__ float g_dz  [NTOK*DIM];
__device__ float g_zc  [NTOK*2*DIM];
__device__ float g_Q   [NTOK*DIM];
__device__ float g_K   [NTOK*DIM];
__device__ float g_V   [NTOK*DIM];
__device__ float g_attn[NTOK*DIM];
__device__ float g_ctx [NTOK*DIM];
__device__ float g_z1  [NTOK*DIM];
__device__ float g_cat3[NTOK*3*DIM];
__device__ float g_hcu [NTOK*2*DIM];
__device__ float g_z1n [NTOK*DIM];
__device__ float g_h4  [NTOK*4*DIM];

// ---------------------------------------------------------------------------
// RMSNorm
// ---------------------------------------------------------------------------
__global__ void rms_kernel(const float* __restrict__ x, const float* __restrict__ w,
                           float* __restrict__ o)
{
    int row = blockIdx.x;
    int t   = threadIdx.x;
    const float4* xr = (const float4*)(x + (size_t)row * DIM);
    float4 v = xr[t];
    float ss = v.x*v.x + v.y*v.y + v.z*v.z + v.w*v.w;

    __shared__ float red[256];
    red[t] = ss;
    __syncthreads();
    for (int s = 128; s > 0; s >>= 1) {
        if (t < s) red[t] += red[t + s];
        __syncthreads();
    }
    float inv = rsqrtf(red[0] * (1.0f / DIM) + 1e-6f);
    float4 wv = ((const float4*)w)[t];
    float4 ov;
    ov.x = v.x * inv * wv.x;
    ov.y = v.y * inv * wv.y;
    ov.z = v.z * inv * wv.z;
    ov.w = v.w * inv * wv.w;
    ((float4*)(o + (size_t)row * DIM))[t] = ov;
}

// ---------------------------------------------------------------------------
// Concats
// ---------------------------------------------------------------------------
__global__ void concat2_kernel(const float* __restrict__ A, const float* __restrict__ B,
                               float* __restrict__ O, int KA, int KB)
{
    int row = blockIdx.x;
    float* orow = O + (size_t)row * (KA + KB);
    const float* a = A + (size_t)row * KA;
    const float* b = B + (size_t)row * KB;
    for (int c = threadIdx.x; c < KA; c += blockDim.x) orow[c] = a[c];
    for (int c = threadIdx.x; c < KB; c += blockDim.x) orow[KA + c] = b[c];
}

__global__ void concat3_kernel(const float* __restrict__ A, const float* __restrict__ B,
                               const float* __restrict__ C, float* __restrict__ O,
                               int KA, int KB, int KC)
{
    int row = blockIdx.x;
    float* orow = O + (size_t)row * (KA + KB + KC);
    const float* a = A + (size_t)row * KA;
    const float* b = B + (size_t)row * KB;
    const float* c = C + (size_t)row * KC;
    for (int i = threadIdx.x; i < KA; i += blockDim.x) orow[i] = a[i];
    for (int i = threadIdx.x; i < KB; i += blockDim.x) orow[KA + i] = b[i];
    for (int i = threadIdx.x; i < KC; i += blockDim.x) orow[KA + KB + i] = c[i];
}

// ---------------------------------------------------------------------------
// Pointwise
// ---------------------------------------------------------------------------
__global__ void dz_kernel(const float* __restrict__ a, const float* __restrict__ b,
                          const float* __restrict__ dt, float* __restrict__ o, int n)
{
    int i = blockIdx.x * blockDim.x + threadIdx.x;
    if (i < n) o[i] = dt[0] * (a[i] + b[i]);
}

__global__ void add3_kernel(const float* __restrict__ a, const float* __restrict__ b,
                            const float* __restrict__ c, float* __restrict__ o, int n)
{
    int i = blockIdx.x * blockDim.x + threadIdx.x;
    if (i < n) o[i] = a[i] + b[i] + c[i];
}

// ---------------------------------------------------------------------------
// TF32 tensor-core GEMM: C = act(A @ W^T + bias) + res
// A [M,K] row-major, W [N,K] row-major. Block tile 128x128x16, 8 warps,
// warp tile 32x64, mma.sync.m16n8k8.tf32, cp.async double-buffered smem.
// Requires M%128==0, N%128==0, K%16==0 (all shapes here satisfy this).
// ---------------------------------------------------------------------------
#define BM 128
#define BN 128
#define BK 16
#define KSTRIDE 20            // BK + 4 pad  -> 80B rows: 16B-aligned, conflict-free

__device__ __forceinline__ uint32_t f2tf32(float f)
{
    uint32_t r;
    asm("cvt.rna.tf32.f32 %0, %1;" : "=r"(r) : "f"(f));
    return r;
}

__device__ __forceinline__ void mma_tf32(float* c, const uint32_t* a, const uint32_t* b)
{
    asm volatile("mma.sync.aligned.m16n8k8.row.col.f32.tf32.tf32.f32 "
                 "{%0,%1,%2,%3}, {%4,%5,%6,%7}, {%8,%9}, {%0,%1,%2,%3};"
                 : "+f"(c[0]), "+f"(c[1]), "+f"(c[2]), "+f"(c[3])
                 : "r"(a[0]), "r"(a[1]), "r"(a[2]), "r"(a[3]),
                   "r"(b[0]), "r"(b[1]));
}

__device__ __forceinline__ void cpasync16(uint32_t saddr, const void* g)
{
    asm volatile("cp.async.cg.shared.global [%0], [%1], 16;\n" :: "r"(saddr), "l"(g));
}

template<int ACT, bool HAS_BIAS, bool HAS_RES>
__global__ __launch_bounds__(256)
void gemm_tc_kernel(const float* __restrict__ A, const float* __restrict__ W,
                    const float* __restrict__ bias, const float* __restrict__ res,
                    float* __restrict__ C, int M, int N, int K)
{
    __shared__ float sA[2][BM][KSTRIDE];
    __shared__ float sW[2][BN][KSTRIDE];

    const int bm = blockIdx.y * BM;
    const int bn = blockIdx.x * BN;
    const int tid  = threadIdx.x;
    const int warp = tid >> 5;
    const int lane = tid & 31;
    const int gid  = lane >> 2;       // group id 0..7
    const int tig  = lane & 3;        // thread in group 0..3
    const int wm   = warp >> 1;       // 0..3 -> 32-row slice
    const int wn   = warp & 1;        // 0..1 -> 64-col slice

    // global load mapping: 512 float4s per tile, 2 per thread
    const int f0   = tid;             // and tid+256
    const int r0   = f0 >> 2,  c0 = (f0 & 3) << 2;
    const int f1   = tid + 256;
    const int r1   = f1 >> 2,  c1 = (f1 & 3) << 2;

    const float* Ab = A + (size_t)bm * K;
    const float* Wb = W + (size_t)bn * K;

    uint32_t sa0 = (uint32_t)__cvta_generic_to_shared(&sA[0][r0][c0]);
    uint32_t sa1 = (uint32_t)__cvta_generic_to_shared(&sA[0][r1][c1]);
    uint32_t sw0 = (uint32_t)__cvta_generic_to_shared(&sW[0][r0][c0]);
    uint32_t sw1 = (uint32_t)__cvta_generic_to_shared(&sW[0][r1][c1]);
    const uint32_t bufoff_a = (uint32_t)(sizeof(float) * BM * KSTRIDE);
    const uint32_t bufoff_w = (uint32_t)(sizeof(float) * BN * KSTRIDE);

    float acc[2][8][4];
    #pragma unroll
    for (int mi = 0; mi < 2; mi++)
        #pragma unroll
        for (int ni = 0; ni < 8; ni++)
            #pragma unroll
            for (int r = 0; r < 4; r++) acc[mi][ni][r] = 0.0f;

    const int KT = K / BK;

    // prefetch tile 0
    cpasync16(sa0, Ab + (size_t)r0 * K + c0);
    cpasync16(sa1, Ab + (size_t)r1 * K + c1);
    cpasync16(sw0, Wb + (size_t)r0 * K + c0);
    cpasync16(sw1, Wb + (size_t)r1 * K + c1);
    asm volatile("cp.async.commit_group;\n");

    int buf = 0;
    for (int kt = 0; kt < KT; kt++) {
        if (kt + 1 < KT) {
            int koff = (kt + 1) * BK;
            uint32_t bo_a = (buf ^ 1) ? bufoff_a : 0;
            uint32_t bo_w = (buf ^ 1) ? bufoff_w : 0;
            cpasync16(sa0 + bo_a, Ab + (size_t)r0 * K + koff + c0);
            cpasync16(sa1 + bo_a, Ab + (size_t)r1 * K + koff + c1);
            cpasync16(sw0 + bo_w, Wb + (size_t)r0 * K + koff + c0);
            cpasync16(sw1 + bo_w, Wb + (size_t)r1 * K + koff + c1);
            asm volatile("cp.async.commit_group;\n");
            asm volatile("cp.async.wait_group 1;\n");
        } else {
            asm volatile("cp.async.wait_group 0;\n");
        }
        __syncthreads();

        #pragma unroll
        for (int k0 = 0; k0 < BK; k0 += 8) {
            uint32_t afr[2][4], bfr[8][2];
            #pragma unroll
            for (int mi = 0; mi < 2; mi++) {
                int rr = wm * 32 + mi * 16 + gid;
                afr[mi][0] = f2tf32(sA[buf][rr    ][k0 + tig    ]);
                afr[mi][1] = f2tf32(sA[buf][rr + 8][k0 + tig    ]);
                afr[mi][2] = f2tf32(sA[buf][rr    ][k0 + tig + 4]);
                afr[mi][3] = f2tf32(sA[buf][rr + 8][k0 + tig + 4]);
            }
            #pragma unroll
            for (int ni = 0; ni < 8; ni++) {
                int cc = wn * 64 + ni * 8 + gid;
                bfr[ni][0] = f2tf32(sW[buf][cc][k0 + tig    ]);
                bfr[ni][1] = f2tf32(sW[buf][cc][k0 + tig + 4]);
            }
            #pragma unroll
            for (int mi = 0; mi < 2; mi++)
                #pragma unroll
                for (int ni = 0; ni < 8; ni++)
                    mma_tf32(acc[mi][ni], afr[mi], bfr[ni]);
        }
        __syncthreads();
        buf ^= 1;
    }

    // epilogue: each thread owns pairs (row, col..col+1) and (row+8, col..col+1)
    #pragma unroll
    for (int mi = 0; mi < 2; mi++) {
        int row = bm + wm * 32 + mi * 16 + gid;
        #pragma unroll
        for (int ni = 0; ni < 8; ni++) {
            int col = bn + wn * 64 + ni * 8 + 2 * tig;
            float b0 = 0.f, b1 = 0.f;
            if (HAS_BIAS) { b0 = bias[col]; b1 = bias[col + 1]; }
            #pragma unroll
            for (int half = 0; half < 2; half++) {
                int r = row + half * 8;
                float v0 = acc[mi][ni][half * 2 + 0] + b0;
                float v1 = acc[mi][ni][half * 2 + 1] + b1;
                if (ACT == 1) { v0 = v0 / (1.0f + __expf(-v0)); v1 = v1 / (1.0f + __expf(-v1)); }
                else if (ACT == 2) { v0 = tanhf(v0); v1 = tanhf(v1); }
                if (HAS_RES) {
                    const float2 rv = *(const float2*)(res + (size_t)r * N + col);
                    v0 += rv.x; v1 += rv.y;
                }
                *(float2*)(C + (size_t)r * N + col) = make_float2(v0, v1);
            }
        }
    }
}

// ---------------------------------------------------------------------------
// Sigmoid attention (flash-style, fp32 SIMT) — unchanged this round
// ---------------------------------------------------------------------------
__global__ void attn_kernel(const float* __restrict__ Q, const float* __restrict__ K,
                            const float* __restrict__ V, const float* __restrict__ temp,
                            float* __restrict__ O)
{
    __shared__ float Qs[64][65];
    __shared__ float Ks[32][65];
    __shared__ float Vs[32][68];
    __shared__ float Ssm[64][33];
    __shared__ float rowsum[64];

    int b = blockIdx.z, h = blockIdx.y;
    int q0 = blockIdx.x * 64;
    int tid = threadIdx.x;
    int ty = tid >> 4, tx = tid & 15;

    const float scale = 0.125f * temp[0];
    const size_t baseq  = ((size_t)(b * SEQ + q0)) * DIM + h * HDIM;
    const size_t basekv = ((size_t)(b * SEQ)) * DIM + h * HDIM;

    #pragma unroll
    for (int it = 0; it < 4; it++) {
        int fid = tid + it * 256;
        int r = fid >> 4, c4 = (fid & 15) * 4;
        float4 v = *(const float4*)(Q + baseq + (size_t)r * DIM + c4);
        Qs[r][c4] = v.x; Qs[r][c4 + 1] = v.y; Qs[r][c4 + 2] = v.z; Qs[r][c4 + 3] = v.w;
    }
    if (tid < 64) rowsum[tid] = 0.0f;

    float oacc[4][4] = {};

    for (int m0 = 0; m0 < SEQ; m0 += 32) {
        __syncthreads();
        #pragma unroll
        for (int it = 0; it < 2; it++) {
            int fid = tid + it * 256;
            int r = fid >> 4, c4 = (fid & 15) * 4;
            float4 kv = *(const float4*)(K + basekv + (size_t)(m0 + r) * DIM + c4);
            Ks[r][c4] = kv.x; Ks[r][c4 + 1] = kv.y; Ks[r][c4 + 2] = kv.z; Ks[r][c4 + 3] = kv.w;
            float4 vv = *(const float4*)(V + basekv + (size_t)(m0 + r) * DIM + c4);
            Vs[r][c4] = vv.x; Vs[r][c4 + 1] = vv.y; Vs[r][c4 + 2] = vv.z; Vs[r][c4 + 3] = vv.w;
        }
        __syncthreads();

        float s0[4] = {}, s1[4] = {};
        int m = tx * 2;
        #pragma unroll 16
        for (int d = 0; d < 64; d++) {
            float b0 = Ks[m][d], b1 = Ks[m + 1][d];
            #pragma unroll
            for (int i = 0; i < 4; i++) {
                float a = Qs[ty * 4 + i][d];
                s0[i] += a * b0;
                s1[i] += a * b1;
            }
        }
        #pragma unroll
        for (int i = 0; i < 4; i++) {
            Ssm[ty * 4 + i][m]     = 1.0f / (1.0f + __expf(-s0[i] * scale));
            Ssm[ty * 4 + i][m + 1] = 1.0f / (1.0f + __expf(-s1[i] * scale));
        }
        __syncthreads();

        if (tid < 64) {
            float rs = 0.0f;
            #pragma unroll
            for (int mm = 0; mm < 32; mm++) rs += Ssm[tid][mm];
            rowsum[tid] += rs;
        }

        #pragma unroll
        for (int mm = 0; mm < 32; mm++) {
            float4 v = *(const float4*)(&Vs[mm][tx * 4]);
            #pragma unroll
            for (int i = 0; i < 4; i++) {
                float s = Ssm[ty * 4 + i][mm];
                oacc[i][0] += s * v.x; oacc[i][1] += s * v.y;
                oacc[i][2] += s * v.z; oacc[i][3] += s * v.w;
            }
        }
    }
    __syncthreads();

    #pragma unroll
    for (int i = 0; i < 4; i++) {
        int r = ty * 4 + i;
        float inv = 1.0f / fmaxf(rowsum[r], 1.0f);
        float4 o4 = make_float4(oacc[i][0] * inv, oacc[i][1] * inv,
                                oacc[i][2] * inv, oacc[i][3] * inv);
        *(float4*)(O + baseq + (size_t)r * DIM + tx * 4) = o4;
    }
}

// ---------------------------------------------------------------------------
// Host-side GEMM dispatch
// ---------------------------------------------------------------------------
static void gemm(const float* A, const float* W, const float* bias, const float* res,
                 float* C, int M, int N, int K, int act)
{
    dim3 g(N / BN, M / BM), b(256);
    if (bias && res) {
        gemm_tc_kernel<0, true, true><<<g, b>>>(A, W, bias, res, C, M, N, K);
    } else if (bias) {
        if (act == 0)      gemm_tc_kernel<0, true, false><<<g, b>>>(A, W, bias, nullptr, C, M, N, K);
        else if (act == 1) gemm_tc_kernel<1, true, false><<<g, b>>>(A, W, bias, nullptr, C, M, N, K);
        else               gemm_tc_kernel<2, true, false><<<g, b>>>(A, W, bias, nullptr, C, M, N, K);
    } else {
        gemm_tc_kernel<0, false, false><<<g, b>>>(A, W, nullptr, nullptr, C, M, N, K);
    }
}

static float* sym(const void* s)
{
    void* p = nullptr;
    cudaGetSymbolAddress(&p, s);
    return (float*)p;
}

extern "C" void kernel_launch(void* const* d_in, const int* in_sizes, int n_in,
                              void* d_out, int out_size)
{
    const float* z     = (const float*)d_in[0];
    const float* conn  = (const float*)d_in[1];
    const float* w_z   = (const float*)d_in[2];
    const float* w_c   = (const float*)d_in[3];
    const float* w_mlp = (const float*)d_in[4];
    const float* f_w1  = (const float*)d_in[5];
    const float* f_b1  = (const float*)d_in[6];
    const float* f_w2  = (const float*)d_in[7];
    const float* f_b2  = (const float*)d_in[8];
    const float* g_w1  = (const float*)d_in[9];
    const float* g_b1  = (const float*)d_in[10];
    const float* g_w2  = (const float*)d_in[11];
    const float* g_b2  = (const float*)d_in[12];
    const float* dt    = (const float*)d_in[13];
    const float* q_w   = (const float*)d_in[14];
    const float* k_w   = (const float*)d_in[15];
    const float* v_w   = (const float*)d_in[16];
    const float* o_w   = (const float*)d_in[17];
    const float* temp  = (const float*)d_in[18];
    const float* cu_w1 = (const float*)d_in[19];
    const float* cu_b1 = (const float*)d_in[20];
    const float* cu_w2 = (const float*)d_in[21];
    const float* cu_b2 = (const float*)d_in[22];
    const float* m_w1  = (const float*)d_in[23];
    const float* m_b1  = (const float*)d_in[24];
    const float* m_w2  = (const float*)d_in[25];
    const float* m_b2  = (const float*)d_in[26];

    float* out_z2 = (float*)d_out;
    float* out_cn = out_z2 + (size_t)NTOK * DIM;
    float* out_zb = out_cn + (size_t)NTOK * DIM;

    float* zn   = sym(g_zn);
    float* cn   = sym(g_cn);
    float* hf   = sym(g_hf);
    float* dzl  = sym(g_dzl);
    float* catg = sym(g_catg);
    float* gh   = sym(g_gh);
    float* corr = sym(g_corr);
    float* dz   = sym(g_dz);
    float* zc   = sym(g_zc);
    float* Qb   = sym(g_Q);
    float* Kb   = sym(g_K);
    float* Vb   = sym(g_V);
    float* attn = sym(g_attn);
    float* ctx  = sym(g_ctx);
    float* z1   = sym(g_z1);
    float* cat3 = sym(g_cat3);
    float* hcu  = sym(g_hcu);
    float* z1n  = sym(g_z1n);
    float* h4   = sym(g_h4);

    const int ND = NTOK * DIM;
    const int PW_BLK = 256;
    const int PW_GRID = ND / PW_BLK;

    // 1. norms
    rms_kernel<<<NTOK, 256>>>(z, w_z, zn);
    rms_kernel<<<NTOK, 256>>>(conn, w_c, cn);

    // 2. vector field F(zn)
    gemm(zn, f_w1, f_b1, nullptr, hf, NTOK, 2 * DIM, DIM, 1);        // silu
    gemm(hf, f_w2, f_b2, nullptr, dzl, NTOK, DIM, 2 * DIM, 0);

    // 3. gamma correction
    concat2_kernel<<<NTOK, 256>>>(cn, dzl, catg, DIM, DIM);
    gemm(catg, g_w1, g_b1, nullptr, gh, NTOK, DIM, 2 * DIM, 2);      // tanh
    gemm(gh, g_w2, g_b2, nullptr, corr, NTOK, DIM, DIM, 0);
    dz_kernel<<<PW_GRID, PW_BLK>>>(dzl, corr, dt, dz, ND);

    // 4. attention projections
    concat2_kernel<<<NTOK, 256>>>(zn, cn, zc, DIM, DIM);
    gemm(zc, q_w, nullptr, nullptr, Qb, NTOK, DIM, 2 * DIM, 0);
    gemm(zc, k_w, nullptr, nullptr, Kb, NTOK, DIM, 2 * DIM, 0);
    gemm(zn, v_w, nullptr, nullptr, Vb, NTOK, DIM, DIM, 0);

    // 5. sigmoid attention
    {
        dim3 g(SEQ / 64, NHEAD, BATCH), b(256);
        attn_kernel<<<g, b>>>(Qb, Kb, Vb, temp, attn);
    }
    gemm(attn, o_w, nullptr, nullptr, ctx, NTOK, DIM, DIM, 0);

    // 6. z1 = z + dz + ctx
    add3_kernel<<<PW_GRID, PW_BLK>>>(z, dz, ctx, z1, ND);

    // 7. connection update
    concat3_kernel<<<NTOK, 256>>>(conn, z1, dz, cat3, DIM, DIM, DIM);
    gemm(cat3, cu_w1, cu_b1, nullptr, hcu, NTOK, 2 * DIM, 3 * DIM, 1);   // silu
    gemm(hcu, cu_w2, cu_b2, conn, out_cn, NTOK, DIM, 2 * DIM, 0);        // + residual

    // 8. MLP block
    rms_kernel<<<NTOK, 256>>>(z1, w_mlp, z1n);
    gemm(z1n, m_w1, m_b1, nullptr, h4, NTOK, 4 * DIM, DIM, 1);           // silu
    gemm(h4, m_w2, m_b2, z1, out_z2, NTOK, DIM, 4 * DIM, 0);             // + residual

    // 9. z_before passthrough
    cudaMemcpyAsync(out_zb, z, (size_t)ND * sizeof(float), cudaMemcpyDeviceToDevice);
}

// round 3
// speedup vs baseline: 3.4951x; 1.2273x over previous
#include <cuda_runtime.h>
#include <math.h>
#include <stdint.h>

#define BATCH 2
#define SEQ   2048
#define DIM   1024
#define NHEAD 16
#define HDIM  64
#define NTOK  (BATCH*SEQ)   // 4096

// ---------------------------------------------------------------------------
// Scratch (static device arrays — runtime alloc is forbidden)
// ---------------------------------------------------------------------------
__device__ float g_zn  [NTOK*DIM];
__device__ float g_cn  [NTOK*DIM];
__device__ float g_hf  [NTOK*2*DIM];
__device__ float g_dzl [NTOK*DIM];
__device__ float g_catg[NTOK*2*DIM];
__device__ float g_gh  [NTOK*DIM];
__device__ float g_corr[NTOK*DIM];
__device__ float g_dz  [NTOK*DIM];
__device__ float g_zc  [NTOK*2*DIM];
__device__ float g_Q   [NTOK*DIM];
__device__ float g_K   [NTOK*DIM];
__device__ float g_V   [NTOK*DIM];
__device__ float g_attn[NTOK*DIM];
__device__ float g_ctx [NTOK*DIM];
__device__ float g_z1  [NTOK*DIM];
__device__ float g_cat3[NTOK*3*DIM];
__device__ float g_hcu [NTOK*2*DIM];
__device__ float g_z1n [NTOK*DIM];
__device__ float g_h4  [NTOK*4*DIM];

// ---------------------------------------------------------------------------
// RMSNorm
// ---------------------------------------------------------------------------
__global__ void rms_kernel(const float* __restrict__ x, const float* __restrict__ w,
                           float* __restrict__ o)
{
    int row = blockIdx.x;
    int t   = threadIdx.x;
    const float4* xr = (const float4*)(x + (size_t)row * DIM);
    float4 v = xr[t];
    float ss = v.x*v.x + v.y*v.y + v.z*v.z + v.w*v.w;

    __shared__ float red[256];
    red[t] = ss;
    __syncthreads();
    for (int s = 128; s > 0; s >>= 1) {
        if (t < s) red[t] += red[t + s];
        __syncthreads();
    }
    float inv = rsqrtf(red[0] * (1.0f / DIM) + 1e-6f);
    float4 wv = ((const float4*)w)[t];
    float4 ov;
    ov.x = v.x * inv * wv.x;
    ov.y = v.y * inv * wv.y;
    ov.z = v.z * inv * wv.z;
    ov.w = v.w * inv * wv.w;
    ((float4*)(o + (size_t)row * DIM))[t] = ov;
}

// ---------------------------------------------------------------------------
// Concats
// ---------------------------------------------------------------------------
__global__ void concat2_kernel(const float* __restrict__ A, const float* __restrict__ B,
                               float* __restrict__ O, int KA, int KB)
{
    int row = blockIdx.x;
    float* orow = O + (size_t)row * (KA + KB);
    const float* a = A + (size_t)row * KA;
    const float* b = B + (size_t)row * KB;
    for (int c = threadIdx.x; c < KA; c += blockDim.x) orow[c] = a[c];
    for (int c = threadIdx.x; c < KB; c += blockDim.x) orow[KA + c] = b[c];
}

__global__ void concat3_kernel(const float* __restrict__ A, const float* __restrict__ B,
                               const float* __restrict__ C, float* __restrict__ O,
                               int KA, int KB, int KC)
{
    int row = blockIdx.x;
    float* orow = O + (size_t)row * (KA + KB + KC);
    const float* a = A + (size_t)row * KA;
    const float* b = B + (size_t)row * KB;
    const float* c = C + (size_t)row * KC;
    for (int i = threadIdx.x; i < KA; i += blockDim.x) orow[i] = a[i];
    for (int i = threadIdx.x; i < KB; i += blockDim.x) orow[KA + i] = b[i];
    for (int i = threadIdx.x; i < KC; i += blockDim.x) orow[KA + KB + i] = c[i];
}

// ---------------------------------------------------------------------------
// Pointwise
// ---------------------------------------------------------------------------
__global__ void dz_kernel(const float* __restrict__ a, const float* __restrict__ b,
                          const float* __restrict__ dt, float* __restrict__ o, int n)
{
    int i = blockIdx.x * blockDim.x + threadIdx.x;
    if (i < n) o[i] = dt[0] * (a[i] + b[i]);
}

__global__ void add3_kernel(const float* __restrict__ a, const float* __restrict__ b,
                            const float* __restrict__ c, float* __restrict__ o, int n)
{
    int i = blockIdx.x * blockDim.x + threadIdx.x;
    if (i < n) o[i] = a[i] + b[i] + c[i];
}

// ---------------------------------------------------------------------------
// mma helpers (tf32; operands are raw fp32 bit patterns — HW truncates)
// ---------------------------------------------------------------------------
__device__ __forceinline__ void mma_tf32(float* c, const uint32_t* a, const uint32_t* b)
{
    asm volatile("mma.sync.aligned.m16n8k8.row.col.f32.tf32.tf32.f32 "
                 "{%0,%1,%2,%3}, {%4,%5,%6,%7}, {%8,%9}, {%0,%1,%2,%3};"
                 : "+f"(c[0]), "+f"(c[1]), "+f"(c[2]), "+f"(c[3])
                 : "r"(a[0]), "r"(a[1]), "r"(a[2]), "r"(a[3]),
                   "r"(b[0]), "r"(b[1]));
}

__device__ __forceinline__ void cpasync16(uint32_t saddr, const void* g)
{
    asm volatile("cp.async.cg.shared.global [%0], [%1], 16;\n" :: "r"(saddr), "l"(g));
}

// ---------------------------------------------------------------------------
// TF32 tensor-core GEMM: C = act(A @ W^T + bias) + res
// Block tile 128x128x16, 8 warps, warp tile 32x64, cp.async double-buffered.
// ---------------------------------------------------------------------------
#define BM 128
#define BN 128
#define BK 16
#define KSTRIDE 20            // BK + 4 pad

template<int ACT, bool HAS_BIAS, bool HAS_RES>
__global__ __launch_bounds__(256)
void gemm_tc_kernel(const float* __restrict__ A, const float* __restrict__ W,
                    const float* __restrict__ bias, const float* __restrict__ res,
                    float* __restrict__ C, int M, int N, int K)
{
    __shared__ float sA[2][BM][KSTRIDE];
    __shared__ float sW[2][BN][KSTRIDE];

    const int bm = blockIdx.y * BM;
    const int bn = blockIdx.x * BN;
    const int tid  = threadIdx.x;
    const int warp = tid >> 5;
    const int lane = tid & 31;
    const int gid  = lane >> 2;
    const int tig  = lane & 3;
    const int wm   = warp >> 1;
    const int wn   = warp & 1;

    const int f0   = tid;
    const int r0   = f0 >> 2,  c0 = (f0 & 3) << 2;
    const int f1   = tid + 256;
    const int r1   = f1 >> 2,  c1 = (f1 & 3) << 2;

    const float* Ab = A + (size_t)bm * K;
    const float* Wb = W + (size_t)bn * K;

    uint32_t sa0 = (uint32_t)__cvta_generic_to_shared(&sA[0][r0][c0]);
    uint32_t sa1 = (uint32_t)__cvta_generic_to_shared(&sA[0][r1][c1]);
    uint32_t sw0 = (uint32_t)__cvta_generic_to_shared(&sW[0][r0][c0]);
    uint32_t sw1 = (uint32_t)__cvta_generic_to_shared(&sW[0][r1][c1]);
    const uint32_t bufoff_a = (uint32_t)(sizeof(float) * BM * KSTRIDE);
    const uint32_t bufoff_w = (uint32_t)(sizeof(float) * BN * KSTRIDE);

    float acc[2][8][4];
    #pragma unroll
    for (int mi = 0; mi < 2; mi++)
        #pragma unroll
        for (int ni = 0; ni < 8; ni++)
            #pragma unroll
            for (int r = 0; r < 4; r++) acc[mi][ni][r] = 0.0f;

    const int KT = K / BK;

    cpasync16(sa0, Ab + (size_t)r0 * K + c0);
    cpasync16(sa1, Ab + (size_t)r1 * K + c1);
    cpasync16(sw0, Wb + (size_t)r0 * K + c0);
    cpasync16(sw1, Wb + (size_t)r1 * K + c1);
    asm volatile("cp.async.commit_group;\n");

    int buf = 0;
    for (int kt = 0; kt < KT; kt++) {
        if (kt + 1 < KT) {
            int koff = (kt + 1) * BK;
            uint32_t bo_a = (buf ^ 1) ? bufoff_a : 0;
            uint32_t bo_w = (buf ^ 1) ? bufoff_w : 0;
            cpasync16(sa0 + bo_a, Ab + (size_t)r0 * K + koff + c0);
            cpasync16(sa1 + bo_a, Ab + (size_t)r1 * K + koff + c1);
            cpasync16(sw0 + bo_w, Wb + (size_t)r0 * K + koff + c0);
            cpasync16(sw1 + bo_w, Wb + (size_t)r1 * K + koff + c1);
            asm volatile("cp.async.commit_group;\n");
            asm volatile("cp.async.wait_group 1;\n");
        } else {
            asm volatile("cp.async.wait_group 0;\n");
        }
        __syncthreads();

        #pragma unroll
        for (int k0 = 0; k0 < BK; k0 += 8) {
            uint32_t afr[2][4], bfr[8][2];
            #pragma unroll
            for (int mi = 0; mi < 2; mi++) {
                int rr = wm * 32 + mi * 16 + gid;
                afr[mi][0] = __float_as_uint(sA[buf][rr    ][k0 + tig    ]);
                afr[mi][1] = __float_as_uint(sA[buf][rr + 8][k0 + tig    ]);
                afr[mi][2] = __float_as_uint(sA[buf][rr    ][k0 + tig + 4]);
                afr[mi][3] = __float_as_uint(sA[buf][rr + 8][k0 + tig + 4]);
            }
            #pragma unroll
            for (int ni = 0; ni < 8; ni++) {
                int cc = wn * 64 + ni * 8 + gid;
                bfr[ni][0] = __float_as_uint(sW[buf][cc][k0 + tig    ]);
                bfr[ni][1] = __float_as_uint(sW[buf][cc][k0 + tig + 4]);
            }
            #pragma unroll
            for (int mi = 0; mi < 2; mi++)
                #pragma unroll
                for (int ni = 0; ni < 8; ni++)
                    mma_tf32(acc[mi][ni], afr[mi], bfr[ni]);
        }
        __syncthreads();
        buf ^= 1;
    }

    #pragma unroll
    for (int mi = 0; mi < 2; mi++) {
        int row = bm + wm * 32 + mi * 16 + gid;
        #pragma unroll
        for (int ni = 0; ni < 8; ni++) {
            int col = bn + wn * 64 + ni * 8 + 2 * tig;
            float b0 = 0.f, b1 = 0.f;
            if (HAS_BIAS) { b0 = bias[col]; b1 = bias[col + 1]; }
            #pragma unroll
            for (int half = 0; half < 2; half++) {
                int r = row + half * 8;
                float v0 = acc[mi][ni][half * 2 + 0] + b0;
                float v1 = acc[mi][ni][half * 2 + 1] + b1;
                if (ACT == 1) { v0 = v0 / (1.0f + __expf(-v0)); v1 = v1 / (1.0f + __expf(-v1)); }
                else if (ACT == 2) { v0 = tanhf(v0); v1 = tanhf(v1); }
                if (HAS_RES) {
                    const float2 rv = *(const float2*)(res + (size_t)r * N + col);
                    v0 += rv.x; v1 += rv.y;
                }
                *(float2*)(C + (size_t)r * N + col) = make_float2(v0, v1);
            }
        }
    }
}

// ---------------------------------------------------------------------------
// Sigmoid attention on tensor cores (tf32 mma, flash-style single pass).
// Block: 128 q-rows of one (b,h); 8 warps (16 q-rows each); KV tiles of 32.
// Q fragments live in registers for the whole kernel (reused by every tile).
// S -> sigmoid -> smem (Ps) -> P@V mma.  attn = (P @ V) / max(rowsum, 1).
// ---------------------------------------------------------------------------
#define AQ  128
#define AKV 32

__global__ __launch_bounds__(256)
void attn_tc_kernel(const float* __restrict__ Q, const float* __restrict__ K,
                    const float* __restrict__ V, const float* __restrict__ temp,
                    float* __restrict__ O)
{
    __shared__ float Ks[AKV][68];     // stride 68: conflict-free (n*68+k)%32 pattern
    __shared__ float Vs[AKV][72];     // stride 72: conflict-free transposed reads
    __shared__ float Ps[AQ][68];

    const int b = blockIdx.z, h = blockIdx.y;
    const int q0 = blockIdx.x * AQ;
    const int tid = threadIdx.x;
    const int warp = tid >> 5, lane = tid & 31;
    const int gid = lane >> 2, tig = lane & 3;

    const float scale = 0.125f * temp[0];     // HD^-0.5 = 1/8
    const size_t baseq  = ((size_t)(b * SEQ + q0)) * DIM + h * HDIM;
    const size_t basekv = ((size_t)(b * SEQ)) * DIM + h * HDIM;

    const int r0 = warp * 16 + gid;           // this thread's S/O rows: r0, r0+8

    // Preload Q fragments (8 k-chunks of 8) — reused for all KV tiles
    uint32_t qfr[8][4];
    {
        const float* Qr0 = Q + baseq + (size_t)r0 * DIM;
        const float* Qr1 = Qr0 + 8 * DIM;
        #pragma unroll
        for (int kc = 0; kc < 8; kc++) {
            qfr[kc][0] = __float_as_uint(Qr0[kc * 8 + tig    ]);
            qfr[kc][1] = __float_as_uint(Qr1[kc * 8 + tig    ]);
            qfr[kc][2] = __float_as_uint(Qr0[kc * 8 + tig + 4]);
            qfr[kc][3] = __float_as_uint(Qr1[kc * 8 + tig + 4]);
        }
    }

    float acc_o[8][4];                        // O tile: 16 rows x 64 hd cols per warp
    #pragma unroll
    for (int nb = 0; nb < 8; nb++)
        #pragma unroll
        for (int r = 0; r < 4; r++) acc_o[nb][r] = 0.0f;
    float rs0 = 0.0f, rs1 = 0.0f;

    for (int m0 = 0; m0 < SEQ; m0 += AKV) {
        __syncthreads();                      // Ks/Vs reuse barrier
        #pragma unroll
        for (int it = 0; it < 2; it++) {
            int f = tid + it * 256;           // 0..511 float4s
            int r = f >> 4, c4 = (f & 15) * 4;
            float4 kv = *(const float4*)(K + basekv + (size_t)(m0 + r) * DIM + c4);
            Ks[r][c4] = kv.x; Ks[r][c4 + 1] = kv.y; Ks[r][c4 + 2] = kv.z; Ks[r][c4 + 3] = kv.w;
            float4 vv = *(const float4*)(V + basekv + (size_t)(m0 + r) * DIM + c4);
            Vs[r][c4] = vv.x; Vs[r][c4 + 1] = vv.y; Vs[r][c4 + 2] = vv.z; Vs[r][c4 + 3] = vv.w;
        }
        __syncthreads();

        // S = Q @ K^T  (warp: 16 x 32)
        float acc_s[4][4] = {};
        #pragma unroll
        for (int kc = 0; kc < 8; kc++) {
            uint32_t bfr[4][2];
            #pragma unroll
            for (int nb = 0; nb < 4; nb++) {
                bfr[nb][0] = __float_as_uint(Ks[nb * 8 + gid][kc * 8 + tig    ]);
                bfr[nb][1] = __float_as_uint(Ks[nb * 8 + gid][kc * 8 + tig + 4]);
            }
            #pragma unroll
            for (int nb = 0; nb < 4; nb++)
                mma_tf32(acc_s[nb], qfr[kc], bfr[nb]);
        }

        // sigmoid + rowsum + park P in smem (only this warp's rows)
        #pragma unroll
        for (int nb = 0; nb < 4; nb++) {
            float s00 = 1.0f / (1.0f + __expf(-acc_s[nb][0] * scale));
            float s01 = 1.0f / (1.0f + __expf(-acc_s[nb][1] * scale));
            float s10 = 1.0f / (1.0f + __expf(-acc_s[nb][2] * scale));
            float s11 = 1.0f / (1.0f + __expf(-acc_s[nb][3] * scale));
            rs0 += s00 + s01;
            rs1 += s10 + s11;
            *(float2*)&Ps[r0    ][nb * 8 + 2 * tig] = make_float2(s00, s01);
            *(float2*)&Ps[r0 + 8][nb * 8 + 2 * tig] = make_float2(s10, s11);
        }
        __syncwarp();                         // Ps rows are warp-private

        // O += P @ V  (warp: 16 x 64, k = 32)
        #pragma unroll
        for (int kc = 0; kc < 4; kc++) {
            uint32_t afr[4];
            afr[0] = __float_as_uint(Ps[r0    ][kc * 8 + tig    ]);
            afr[1] = __float_as_uint(Ps[r0 + 8][kc * 8 + tig    ]);
            afr[2] = __float_as_uint(Ps[r0    ][kc * 8 + tig + 4]);
            afr[3] = __float_as_uint(Ps[r0 + 8][kc * 8 + tig + 4]);
            #pragma unroll
            for (int nb = 0; nb < 8; nb++) {
                uint32_t bfr[2];
                bfr[0] = __float_as_uint(Vs[kc * 8 + tig    ][nb * 8 + gid]);
                bfr[1] = __float_as_uint(Vs[kc * 8 + tig + 4][nb * 8 + gid]);
                mma_tf32(acc_o[nb], afr, bfr);
            }
        }
        __syncwarp();                         // Ps rewritten next iteration (warp-local)
    }

    // rowsum: sum across tig (4 threads per gid hold disjoint columns)
    rs0 += __shfl_xor_sync(0xffffffffu, rs0, 1);
    rs0 += __shfl_xor_sync(0xffffffffu, rs0, 2);
    rs1 += __shfl_xor_sync(0xffffffffu, rs1, 1);
    rs1 += __shfl_xor_sync(0xffffffffu, rs1, 2);
    const float inv0 = 1.0f / fmaxf(rs0, 1.0f);
    const float inv1 = 1.0f / fmaxf(rs1, 1.0f);

    float* O0 = O + baseq + (size_t)r0 * DIM;
    float* O1 = O0 + 8 * DIM;
    #pragma unroll
    for (int nb = 0; nb < 8; nb++) {
        int col = nb * 8 + 2 * tig;
        *(float2*)(O0 + col) = make_float2(acc_o[nb][0] * inv0, acc_o[nb][1] * inv0);
        *(float2*)(O1 + col) = make_float2(acc_o[nb][2] * inv1, acc_o[nb][3] * inv1);
    }
}

// ---------------------------------------------------------------------------
// Host-side GEMM dispatch
// ---------------------------------------------------------------------------
static void gemm(const float* A, const float* W, const float* bias, const float* res,
                 float* C, int M, int N, int K, int act)
{
    dim3 g(N / BN, M / BM), b(256);
    if (bias && res) {
        gemm_tc_kernel<0, true, true><<<g, b>>>(A, W, bias, res, C, M, N, K);
    } else if (bias) {
        if (act == 0)      gemm_tc_kernel<0, true, false><<<g, b>>>(A, W, bias, nullptr, C, M, N, K);
        else if (act == 1) gemm_tc_kernel<1, true, false><<<g, b>>>(A, W, bias, nullptr, C, M, N, K);
        else               gemm_tc_kernel<2, true, false><<<g, b>>>(A, W, bias, nullptr, C, M, N, K);
    } else {
        gemm_tc_kernel<0, false, false><<<g, b>>>(A, W, nullptr, nullptr, C, M, N, K);
    }
}

static float* sym(const void* s)
{
    void* p = nullptr;
    cudaGetSymbolAddress(&p, s);
    return (float*)p;
}

extern "C" void kernel_launch(void* const* d_in, const int* in_sizes, int n_in,
                              void* d_out, int out_size)
{
    const float* z     = (const float*)d_in[0];
    const float* conn  = (const float*)d_in[1];
    const float* w_z   = (const float*)d_in[2];
    const float* w_c   = (const float*)d_in[3];
    const float* w_mlp = (const float*)d_in[4];
    const float* f_w1  = (const float*)d_in[5];
    const float* f_b1  = (const float*)d_in[6];
    const float* f_w2  = (const float*)d_in[7];
    const float* f_b2  = (const float*)d_in[8];
    const float* g_w1  = (const float*)d_in[9];
    const float* g_b1  = (const float*)d_in[10];
    const float* g_w2  = (const float*)d_in[11];
    const float* g_b2  = (const float*)d_in[12];
    const float* dt    = (const float*)d_in[13];
    const float* q_w   = (const float*)d_in[14];
    const float* k_w   = (const float*)d_in[15];
    const float* v_w   = (const float*)d_in[16];
    const float* o_w   = (const float*)d_in[17];
    const float* temp  = (const float*)d_in[18];
    const float* cu_w1 = (const float*)d_in[19];
    const float* cu_b1 = (const float*)d_in[20];
    const float* cu_w2 = (const float*)d_in[21];
    const float* cu_b2 = (const float*)d_in[22];
    const float* m_w1  = (const float*)d_in[23];
    const float* m_b1  = (const float*)d_in[24];
    const float* m_w2  = (const float*)d_in[25];
    const float* m_b2  = (const float*)d_in[26];

    float* out_z2 = (float*)d_out;
    float* out_cn = out_z2 + (size_t)NTOK * DIM;
    float* out_zb = out_cn + (size_t)NTOK * DIM;

    float* zn   = sym(g_zn);
    float* cn   = sym(g_cn);
    float* hf   = sym(g_hf);
    float* dzl  = sym(g_dzl);
    float* catg = sym(g_catg);
    float* gh   = sym(g_gh);
    float* corr = sym(g_corr);
    float* dz   = sym(g_dz);
    float* zc   = sym(g_zc);
    float* Qb   = sym(g_Q);
    float* Kb   = sym(g_K);
    float* Vb   = sym(g_V);
    float* attn = sym(g_attn);
    float* ctx  = sym(g_ctx);
    float* z1   = sym(g_z1);
    float* cat3 = sym(g_cat3);
    float* hcu  = sym(g_hcu);
    float* z1n  = sym(g_z1n);
    float* h4   = sym(g_h4);

    const int ND = NTOK * DIM;
    const int PW_BLK = 256;
    const int PW_GRID = ND / PW_BLK;

    // 1. norms
    rms_kernel<<<NTOK, 256>>>(z, w_z, zn);
    rms_kernel<<<NTOK, 256>>>(conn, w_c, cn);

    // 2. vector field F(zn)
    gemm(zn, f_w1, f_b1, nullptr, hf, NTOK, 2 * DIM, DIM, 1);        // silu
    gemm(hf, f_w2, f_b2, nullptr, dzl, NTOK, DIM, 2 * DIM, 0);

    // 3. gamma correction
    concat2_kernel<<<NTOK, 256>>>(cn, dzl, catg, DIM, DIM);
    gemm(catg, g_w1, g_b1, nullptr, gh, NTOK, DIM, 2 * DIM, 2);      // tanh
    gemm(gh, g_w2, g_b2, nullptr, corr, NTOK, DIM, DIM, 0);
    dz_kernel<<<PW_GRID, PW_BLK>>>(dzl, corr, dt, dz, ND);

    // 4. attention projections
    concat2_kernel<<<NTOK, 256>>>(zn, cn, zc, DIM, DIM);
    gemm(zc, q_w, nullptr, nullptr, Qb, NTOK, DIM, 2 * DIM, 0);
    gemm(zc, k_w, nullptr, nullptr, Kb, NTOK, DIM, 2 * DIM, 0);
    gemm(zn, v_w, nullptr, nullptr, Vb, NTOK, DIM, DIM, 0);

    // 5. sigmoid attention (tensor cores)
    {
        dim3 g(SEQ / AQ, NHEAD, BATCH), b(256);
        attn_tc_kernel<<<g, b>>>(Qb, Kb, Vb, temp, attn);
    }
    gemm(attn, o_w, nullptr, nullptr, ctx, NTOK, DIM, DIM, 0);

    // 6. z1 = z + dz + ctx
    add3_kernel<<<PW_GRID, PW_BLK>>>(z, dz, ctx, z1, ND);

    // 7. connection update
    concat3_kernel<<<NTOK, 256>>>(conn, z1, dz, cat3, DIM, DIM, DIM);
    gemm(cat3, cu_w1, cu_b1, nullptr, hcu, NTOK, 2 * DIM, 3 * DIM, 1);   // silu
    gemm(hcu, cu_w2, cu_b2, conn, out_cn, NTOK, DIM, 2 * DIM, 0);        // + residual

    // 8. MLP block
    rms_kernel<<<NTOK, 256>>>(z1, w_mlp, z1n);
    gemm(z1n, m_w1, m_b1, nullptr, h4, NTOK, 4 * DIM, DIM, 1);           // silu
    gemm(h4, m_w2, m_b2, z1, out_z2, NTOK, DIM, 4 * DIM, 0);             // + residual

    // 9. z_before passthrough
    cudaMemcpyAsync(out_zb, z, (size_t)ND * sizeof(float), cudaMemcpyDeviceToDevice);
}

// round 4
// speedup vs baseline: 3.6769x; 1.0520x over previous
#include <cuda_runtime.h>
#include <math.h>
#include <stdint.h>

#define BATCH 2
#define SEQ   2048
#define DIM   1024
#define NHEAD 16
#define HDIM  64
#define NTOK  (BATCH*SEQ)   // 4096

// ---------------------------------------------------------------------------
// Scratch (static device arrays — runtime alloc is forbidden)
// ---------------------------------------------------------------------------
__device__ float g_zn  [NTOK*DIM];
__device__ float g_cn  [NTOK*DIM];
__device__ float g_hf  [NTOK*2*DIM];
__device__ float g_dzl [NTOK*DIM];
__device__ float g_gh  [NTOK*DIM];
__device__ float g_dz  [NTOK*DIM];
__device__ float g_Q   [NTOK*DIM];
__device__ float g_K   [NTOK*DIM];
__device__ float g_V   [NTOK*DIM];
__device__ float g_attn[NTOK*DIM];
__device__ float g_z1  [NTOK*DIM];
__device__ float g_hcu [NTOK*2*DIM];
__device__ float g_z1n [NTOK*DIM];
__device__ float g_h4  [NTOK*4*DIM];

// ---------------------------------------------------------------------------
// RMSNorm
// ---------------------------------------------------------------------------
__global__ void rms_kernel(const float* __restrict__ x, const float* __restrict__ w,
                           float* __restrict__ o)
{
    int row = blockIdx.x;
    int t   = threadIdx.x;
    const float4* xr = (const float4*)(x + (size_t)row * DIM);
    float4 v = xr[t];
    float ss = v.x*v.x + v.y*v.y + v.z*v.z + v.w*v.w;

    __shared__ float red[256];
    red[t] = ss;
    __syncthreads();
    for (int s = 128; s > 0; s >>= 1) {
        if (t < s) red[t] += red[t + s];
        __syncthreads();
    }
    float inv = rsqrtf(red[0] * (1.0f / DIM) + 1e-6f);
    float4 wv = ((const float4*)w)[t];
    float4 ov;
    ov.x = v.x * inv * wv.x;
    ov.y = v.y * inv * wv.y;
    ov.z = v.z * inv * wv.z;
    ov.w = v.w * inv * wv.w;
    ((float4*)(o + (size_t)row * DIM))[t] = ov;
}

// ---------------------------------------------------------------------------
// mma helpers (tf32 with rna rounding — restores R2 error level at no cost)
// ---------------------------------------------------------------------------
__device__ __forceinline__ uint32_t f2tf32(float f)
{
    uint32_t r;
    asm("cvt.rna.tf32.f32 %0, %1;" : "=r"(r) : "f"(f));
    return r;
}

__device__ __forceinline__ void mma_tf32(float* c, const uint32_t* a, const uint32_t* b)
{
    asm volatile("mma.sync.aligned.m16n8k8.row.col.f32.tf32.tf32.f32 "
                 "{%0,%1,%2,%3}, {%4,%5,%6,%7}, {%8,%9}, {%0,%1,%2,%3};"
                 : "+f"(c[0]), "+f"(c[1]), "+f"(c[2]), "+f"(c[3])
                 : "r"(a[0]), "r"(a[1]), "r"(a[2]), "r"(a[3]),
                   "r"(b[0]), "r"(b[1]));
}

__device__ __forceinline__ void cpasync16(uint32_t saddr, const void* g)
{
    asm volatile("cp.async.cg.shared.global [%0], [%1], 16;\n" :: "r"(saddr), "l"(g));
}

// ---------------------------------------------------------------------------
// TF32 tensor-core GEMM with segmented-A gather and fused epilogues.
//   C = EPI( ACT( gatherA @ W^T + bias ) )
// A is given as up to 4 K-segments of width 1024 (concat fusion); segment s
// covers global k in [1024*s, 1024*(s+1)), with its own base ptr + row stride.
// Block tile 128x128x32, 8 warps (warp tile 32x64), cp.async double-buffered
// dynamic smem (73.7 KB), __launch_bounds__(256,2) for 2 CTAs/SM.
// EPI: 0 none | 1 +res1 | 2 dt*(res1+v) | 3 v+res1+res2
// ACT: 0 none | 1 silu | 2 tanh
// ---------------------------------------------------------------------------
#define BM 128
#define BN 128
#define BK 32
#define KST 36                          // BK + 4 pad
#define SA_FLOATS (BM * KST)            // one stage, one matrix
#define GEMM_SMEM (4 * SA_FLOATS * 4)   // 2 stages x 2 matrices, bytes

template<int ACT, int EPI, bool HAS_BIAS>
__global__ __launch_bounds__(256, 2)
void gemm_tc_kernel(const float* __restrict__ p0, const float* __restrict__ p1,
                    const float* __restrict__ p2, const float* __restrict__ p3,
                    int s0, int s1, int s2, int s3,
                    const float* __restrict__ W,
                    const float* __restrict__ bias,
                    const float* __restrict__ res1, const float* __restrict__ res2,
                    const float* __restrict__ dtp,
                    float* __restrict__ C, int M, int N, int K)
{
    extern __shared__ float dsm[];
    // layout: [sA stage0][sA stage1][sW stage0][sW stage1]
    const uint32_t smem0 = (uint32_t)__cvta_generic_to_shared(dsm);

    const int bm = blockIdx.y * BM;
    const int bn = blockIdx.x * BN;
    const int tid  = threadIdx.x;
    const int warp = tid >> 5;
    const int lane = tid & 31;
    const int gid  = lane >> 2;
    const int tig  = lane & 3;
    const int wm   = warp >> 1;
    const int wn   = warp & 1;

    // loader mapping: 1024 float4s per matrix per tile, 4 per thread
    const int rbase = tid >> 3;         // row advances by 32 per it
    const int c4    = (tid & 7) * 4;    // float col within BK

    float acc[2][8][4];
    #pragma unroll
    for (int mi = 0; mi < 2; mi++)
        #pragma unroll
        for (int ni = 0; ni < 8; ni++)
            #pragma unroll
            for (int r = 0; r < 4; r++) acc[mi][ni][r] = 0.0f;

    const int KT = K / BK;

    // prefetch helper (inlined twice)
    #define PREFETCH(KT_IDX, BUF)                                                   \
    {                                                                               \
        const int gk  = (KT_IDX) * BK;                                              \
        const int seg = gk >> 10;                                                   \
        const float* sp = (seg == 0) ? p0 : (seg == 1) ? p1 : (seg == 2) ? p2 : p3; \
        const int    st = (seg == 0) ? s0 : (seg == 1) ? s1 : (seg == 2) ? s2 : s3; \
        const int    ko = (gk & 1023) + c4;                                         \
        _Pragma("unroll")                                                           \
        for (int it = 0; it < 4; it++) {                                            \
            int r = rbase + it * 32;                                                \
            uint32_t da = smem0 + ((BUF) * SA_FLOATS + r * KST + c4) * 4;           \
            cpasync16(da, sp + (size_t)(bm + r) * st + ko);                         \
            uint32_t dw = smem0 + ((2 + (BUF)) * SA_FLOATS + r * KST + c4) * 4;     \
            cpasync16(dw, W + (size_t)(bn + r) * K + gk + c4);                      \
        }                                                                           \
        asm volatile("cp.async.commit_group;\n");                                   \
    }

    PREFETCH(0, 0);

    int buf = 0;
    for (int kt = 0; kt < KT; kt++) {
        if (kt + 1 < KT) {
            PREFETCH(kt + 1, buf ^ 1);
            asm volatile("cp.async.wait_group 1;\n");
        } else {
            asm volatile("cp.async.wait_group 0;\n");
        }
        __syncthreads();

        const float* sA = dsm + buf * SA_FLOATS;
        const float* sW = dsm + (2 + buf) * SA_FLOATS;

        #pragma unroll
        for (int k0 = 0; k0 < BK; k0 += 8) {
            uint32_t afr[2][4], bfr[8][2];
            #pragma unroll
            for (int mi = 0; mi < 2; mi++) {
                int rr = wm * 32 + mi * 16 + gid;
                afr[mi][0] = f2tf32(sA[(rr    ) * KST + k0 + tig    ]);
                afr[mi][1] = f2tf32(sA[(rr + 8) * KST + k0 + tig    ]);
                afr[mi][2] = f2tf32(sA[(rr    ) * KST + k0 + tig + 4]);
                afr[mi][3] = f2tf32(sA[(rr + 8) * KST + k0 + tig + 4]);
            }
            #pragma unroll
            for (int ni = 0; ni < 8; ni++) {
                int cc = wn * 64 + ni * 8 + gid;
                bfr[ni][0] = f2tf32(sW[cc * KST + k0 + tig    ]);
                bfr[ni][1] = f2tf32(sW[cc * KST + k0 + tig + 4]);
            }
            #pragma unroll
            for (int mi = 0; mi < 2; mi++)
                #pragma unroll
                for (int ni = 0; ni < 8; ni++)
                    mma_tf32(acc[mi][ni], afr[mi], bfr[ni]);
        }
        __syncthreads();
        buf ^= 1;
    }
    #undef PREFETCH

    const float dtv = (EPI == 2) ? dtp[0] : 0.0f;

    #pragma unroll
    for (int mi = 0; mi < 2; mi++) {
        int row = bm + wm * 32 + mi * 16 + gid;
        #pragma unroll
        for (int ni = 0; ni < 8; ni++) {
            int col = bn + wn * 64 + ni * 8 + 2 * tig;
            float b0 = 0.f, b1 = 0.f;
            if (HAS_BIAS) { b0 = bias[col]; b1 = bias[col + 1]; }
            #pragma unroll
            for (int half = 0; half < 2; half++) {
                int r = row + half * 8;
                float v0 = acc[mi][ni][half * 2 + 0] + b0;
                float v1 = acc[mi][ni][half * 2 + 1] + b1;
                if (ACT == 1) { v0 = v0 / (1.0f + __expf(-v0)); v1 = v1 / (1.0f + __expf(-v1)); }
                else if (ACT == 2) { v0 = tanhf(v0); v1 = tanhf(v1); }
                if (EPI == 1) {
                    const float2 rv = *(const float2*)(res1 + (size_t)r * N + col);
                    v0 += rv.x; v1 += rv.y;
                } else if (EPI == 2) {
                    const float2 rv = *(const float2*)(res1 + (size_t)r * N + col);
                    v0 = dtv * (rv.x + v0); v1 = dtv * (rv.y + v1);
                } else if (EPI == 3) {
                    const float2 ra = *(const float2*)(res1 + (size_t)r * N + col);
                    const float2 rb = *(const float2*)(res2 + (size_t)r * N + col);
                    v0 += ra.x + rb.x; v1 += ra.y + rb.y;
                }
                *(float2*)(C + (size_t)r * N + col) = make_float2(v0, v1);
            }
        }
    }
}

// ---------------------------------------------------------------------------
// Sigmoid attention on tensor cores (tf32 mma, flash-style single pass).
// ---------------------------------------------------------------------------
#define AQ  128
#define AKV 32

__global__ __launch_bounds__(256)
void attn_tc_kernel(const float* __restrict__ Q, const float* __restrict__ K,
                    const float* __restrict__ V, const float* __restrict__ temp,
                    float* __restrict__ O)
{
    __shared__ float Ks[AKV][68];
    __shared__ float Vs[AKV][72];
    __shared__ float Ps[AQ][68];

    const int b = blockIdx.z, h = blockIdx.y;
    const int q0 = blockIdx.x * AQ;
    const int tid = threadIdx.x;
    const int warp = tid >> 5, lane = tid & 31;
    const int gid = lane >> 2, tig = lane & 3;

    const float scale = 0.125f * temp[0];
    const size_t baseq  = ((size_t)(b * SEQ + q0)) * DIM + h * HDIM;
    const size_t basekv = ((size_t)(b * SEQ)) * DIM + h * HDIM;

    const int r0 = warp * 16 + gid;

    uint32_t qfr[8][4];
    {
        const float* Qr0 = Q + baseq + (size_t)r0 * DIM;
        const float* Qr1 = Qr0 + 8 * DIM;
        #pragma unroll
        for (int kc = 0; kc < 8; kc++) {
            qfr[kc][0] = f2tf32(Qr0[kc * 8 + tig    ]);
            qfr[kc][1] = f2tf32(Qr1[kc * 8 + tig    ]);
            qfr[kc][2] = f2tf32(Qr0[kc * 8 + tig + 4]);
            qfr[kc][3] = f2tf32(Qr1[kc * 8 + tig + 4]);
        }
    }

    float acc_o[8][4];
    #pragma unroll
    for (int nb = 0; nb < 8; nb++)
        #pragma unroll
        for (int r = 0; r < 4; r++) acc_o[nb][r] = 0.0f;
    float rs0 = 0.0f, rs1 = 0.0f;

    for (int m0 = 0; m0 < SEQ; m0 += AKV) {
        __syncthreads();
        #pragma unroll
        for (int it = 0; it < 2; it++) {
            int f = tid + it * 256;
            int r = f >> 4, c4 = (f & 15) * 4;
            float4 kv = *(const float4*)(K + basekv + (size_t)(m0 + r) * DIM + c4);
            Ks[r][c4] = kv.x; Ks[r][c4 + 1] = kv.y; Ks[r][c4 + 2] = kv.z; Ks[r][c4 + 3] = kv.w;
            float4 vv = *(const float4*)(V + basekv + (size_t)(m0 + r) * DIM + c4);
            Vs[r][c4] = vv.x; Vs[r][c4 + 1] = vv.y; Vs[r][c4 + 2] = vv.z; Vs[r][c4 + 3] = vv.w;
        }
        __syncthreads();

        float acc_s[4][4] = {};
        #pragma unroll
        for (int kc = 0; kc < 8; kc++) {
            uint32_t bfr[4][2];
            #pragma unroll
            for (int nb = 0; nb < 4; nb++) {
                bfr[nb][0] = f2tf32(Ks[nb * 8 + gid][kc * 8 + tig    ]);
                bfr[nb][1] = f2tf32(Ks[nb * 8 + gid][kc * 8 + tig + 4]);
            }
            #pragma unroll
            for (int nb = 0; nb < 4; nb++)
                mma_tf32(acc_s[nb], qfr[kc], bfr[nb]);
        }

        #pragma unroll
        for (int nb = 0; nb < 4; nb++) {
            float s00 = 1.0f / (1.0f + __expf(-acc_s[nb][0] * scale));
            float s01 = 1.0f / (1.0f + __expf(-acc_s[nb][1] * scale));
            float s10 = 1.0f / (1.0f + __expf(-acc_s[nb][2] * scale));
            float s11 = 1.0f / (1.0f + __expf(-acc_s[nb][3] * scale));
            rs0 += s00 + s01;
            rs1 += s10 + s11;
            *(float2*)&Ps[r0    ][nb * 8 + 2 * tig] = make_float2(s00, s01);
            *(float2*)&Ps[r0 + 8][nb * 8 + 2 * tig] = make_float2(s10, s11);
        }
        __syncwarp();

        #pragma unroll
        for (int kc = 0; kc < 4; kc++) {
            uint32_t afr[4];
            afr[0] = f2tf32(Ps[r0    ][kc * 8 + tig    ]);
            afr[1] = f2tf32(Ps[r0 + 8][kc * 8 + tig    ]);
            afr[2] = f2tf32(Ps[r0    ][kc * 8 + tig + 4]);
            afr[3] = f2tf32(Ps[r0 + 8][kc * 8 + tig + 4]);
            #pragma unroll
            for (int nb = 0; nb < 8; nb++) {
                uint32_t bfr[2];
                bfr[0] = f2tf32(Vs[kc * 8 + tig    ][nb * 8 + gid]);
                bfr[1] = f2tf32(Vs[kc * 8 + tig + 4][nb * 8 + gid]);
                mma_tf32(acc_o[nb], afr, bfr);
            }
        }
        __syncwarp();
    }

    rs0 += __shfl_xor_sync(0xffffffffu, rs0, 1);
    rs0 += __shfl_xor_sync(0xffffffffu, rs0, 2);
    rs1 += __shfl_xor_sync(0xffffffffu, rs1, 1);
    rs1 += __shfl_xor_sync(0xffffffffu, rs1, 2);
    const float inv0 = 1.0f / fmaxf(rs0, 1.0f);
    const float inv1 = 1.0f / fmaxf(rs1, 1.0f);

    float* O0 = O + baseq + (size_t)r0 * DIM;
    float* O1 = O0 + 8 * DIM;
    #pragma unroll
    for (int nb = 0; nb < 8; nb++) {
        int col = nb * 8 + 2 * tig;
        *(float2*)(O0 + col) = make_float2(acc_o[nb][0] * inv0, acc_o[nb][1] * inv0);
        *(float2*)(O1 + col) = make_float2(acc_o[nb][2] * inv1, acc_o[nb][3] * inv1);
    }
}

// ---------------------------------------------------------------------------
// Host-side dispatch
// ---------------------------------------------------------------------------
struct Seg { const float* p; int s; };

template<int ACT, int EPI, bool HAS_BIAS>
static void launch_gemm(const Seg* seg, int nseg, const float* W, const float* bias,
                        const float* res1, const float* res2, const float* dtp,
                        float* C, int M, int N, int K)
{
    cudaFuncSetAttribute(gemm_tc_kernel<ACT, EPI, HAS_BIAS>,
                         cudaFuncAttributeMaxDynamicSharedMemorySize, GEMM_SMEM);
    const float* p0 = seg[0].p;                     int s0 = seg[0].s;
    const float* p1 = (nseg > 1) ? seg[1].p : p0;   int s1 = (nseg > 1) ? seg[1].s : s0;
    const float* p2 = (nseg > 2) ? seg[2].p : p0;   int s2 = (nseg > 2) ? seg[2].s : s0;
    const float* p3 = (nseg > 3) ? seg[3].p : p0;   int s3 = (nseg > 3) ? seg[3].s : s0;
    dim3 g(N / BN, M / BM), b(256);
    gemm_tc_kernel<ACT, EPI, HAS_BIAS><<<g, b, GEMM_SMEM>>>(
        p0, p1, p2, p3, s0, s1, s2, s3, W, bias, res1, res2, dtp, C, M, N, K);
}

static float* sym(const void* s)
{
    void* p = nullptr;
    cudaGetSymbolAddress(&p, s);
    return (float*)p;
}

extern "C" void kernel_launch(void* const* d_in, const int* in_sizes, int n_in,
                              void* d_out, int out_size)
{
    const float* z     = (const float*)d_in[0];
    const float* conn  = (const float*)d_in[1];
    const float* w_z   = (const float*)d_in[2];
    const float* w_c   = (const float*)d_in[3];
    const float* w_mlp = (const float*)d_in[4];
    const float* f_w1  = (const float*)d_in[5];
    const float* f_b1  = (const float*)d_in[6];
    const float* f_w2  = (const float*)d_in[7];
    const float* f_b2  = (const float*)d_in[8];
    const float* g_w1  = (const float*)d_in[9];
    const float* g_b1  = (const float*)d_in[10];
    const float* g_w2  = (const float*)d_in[11];
    const float* g_b2  = (const float*)d_in[12];
    const float* dt    = (const float*)d_in[13];
    const float* q_w   = (const float*)d_in[14];
    const float* k_w   = (const float*)d_in[15];
    const float* v_w   = (const float*)d_in[16];
    const float* o_w   = (const float*)d_in[17];
    const float* temp  = (const float*)d_in[18];
    const float* cu_w1 = (const float*)d_in[19];
    const float* cu_b1 = (const float*)d_in[20];
    const float* cu_w2 = (const float*)d_in[21];
    const float* cu_b2 = (const float*)d_in[22];
    const float* m_w1  = (const float*)d_in[23];
    const float* m_b1  = (const float*)d_in[24];
    const float* m_w2  = (const float*)d_in[25];
    const float* m_b2  = (const float*)d_in[26];

    float* out_z2 = (float*)d_out;
    float* out_cn = out_z2 + (size_t)NTOK * DIM;
    float* out_zb = out_cn + (size_t)NTOK * DIM;

    float* zn   = sym(g_zn);
    float* cn   = sym(g_cn);
    float* hf   = sym(g_hf);
    float* dzl  = sym(g_dzl);
    float* gh   = sym(g_gh);
    float* dz   = sym(g_dz);
    float* Qb   = sym(g_Q);
    float* Kb   = sym(g_K);
    float* Vb   = sym(g_V);
    float* attn = sym(g_attn);
    float* z1   = sym(g_z1);
    float* hcu  = sym(g_hcu);
    float* z1n  = sym(g_z1n);
    float* h4   = sym(g_h4);

    const int ND = NTOK * DIM;

    // 1. norms
    rms_kernel<<<NTOK, 256>>>(z, w_z, zn);
    rms_kernel<<<NTOK, 256>>>(conn, w_c, cn);

    // 2. vector field F(zn):  hf = silu(zn @ f_w1^T + f_b1); dzl = hf @ f_w2^T + f_b2
    { Seg s[1] = {{zn, DIM}};
      launch_gemm<1,0,true>(s, 1, f_w1, f_b1, nullptr, nullptr, nullptr, hf, NTOK, 2*DIM, DIM); }
    { Seg s[2] = {{hf, 2*DIM}, {hf + DIM, 2*DIM}};
      launch_gemm<0,0,true>(s, 2, f_w2, f_b2, nullptr, nullptr, nullptr, dzl, NTOK, DIM, 2*DIM); }

    // 3. gamma: gh = tanh([cn,dzl] @ g_w1^T + g_b1); dz = dt*(dzl + gh @ g_w2^T + g_b2)
    { Seg s[2] = {{cn, DIM}, {dzl, DIM}};
      launch_gemm<2,0,true>(s, 2, g_w1, g_b1, nullptr, nullptr, nullptr, gh, NTOK, DIM, 2*DIM); }
    { Seg s[1] = {{gh, DIM}};
      launch_gemm<0,2,true>(s, 1, g_w2, g_b2, dzl, nullptr, dt, dz, NTOK, DIM, DIM); }

    // 4. attention projections from [zn,cn] (concat fused into gather)
    { Seg s[2] = {{zn, DIM}, {cn, DIM}};
      launch_gemm<0,0,false>(s, 2, q_w, nullptr, nullptr, nullptr, nullptr, Qb, NTOK, DIM, 2*DIM);
      launch_gemm<0,0,false>(s, 2, k_w, nullptr, nullptr, nullptr, nullptr, Kb, NTOK, DIM, 2*DIM); }
    { Seg s[1] = {{zn, DIM}};
      launch_gemm<0,0,false>(s, 1, v_w, nullptr, nullptr, nullptr, nullptr, Vb, NTOK, DIM, DIM); }

    // 5. sigmoid attention
    {
        dim3 g(SEQ / AQ, NHEAD, BATCH), b(256);
        attn_tc_kernel<<<g, b>>>(Qb, Kb, Vb, temp, attn);
    }

    // 6. z1 = z + dz + attn @ o_w^T   (add3 fused into epilogue)
    { Seg s[1] = {{attn, DIM}};
      launch_gemm<0,3,false>(s, 1, o_w, nullptr, z, dz, nullptr, z1, NTOK, DIM, DIM); }

    // 7. connection update: hcu = silu([conn,z1,dz] @ cu_w1^T + cu_b1);
    //    out_cn = conn + hcu @ cu_w2^T + cu_b2
    { Seg s[3] = {{conn, DIM}, {z1, DIM}, {dz, DIM}};
      launch_gemm<1,0,true>(s, 3, cu_w1, cu_b1, nullptr, nullptr, nullptr, hcu, NTOK, 2*DIM, 3*DIM); }
    { Seg s[2] = {{hcu, 2*DIM}, {hcu + DIM, 2*DIM}};
      launch_gemm<0,1,true>(s, 2, cu_w2, cu_b2, conn, nullptr, nullptr, out_cn, NTOK, DIM, 2*DIM); }

    // 8. MLP block: out_z2 = z1 + silu(rms(z1) @ m_w1^T + m_b1) @ m_w2^T + m_b2
    rms_kernel<<<NTOK, 256>>>(z1, w_mlp, z1n);
    { Seg s[1] = {{z1n, DIM}};
      launch_gemm<1,0,true>(s, 1, m_w1, m_b1, nullptr, nullptr, nullptr, h4, NTOK, 4*DIM, DIM); }
    { Seg s[4] = {{h4, 4*DIM}, {h4 + DIM, 4*DIM}, {h4 + 2*DIM, 4*DIM}, {h4 + 3*DIM, 4*DIM}};
      launch_gemm<0,1,true>(s, 4, m_w2, m_b2, z1, nullptr, nullptr, out_z2, NTOK, DIM, 4*DIM); }

    // 9. z_before passthrough
    cudaMemcpyAsync(out_zb, z, (size_t)ND * sizeof(float), cudaMemcpyDeviceToDevice);
}